// round 3
// baseline (speedup 1.0000x reference)
#include <cuda_runtime.h>
#include <math.h>

// Problem constants (fixed by the dataset)
#define NMAX 100000
#define C_IN 64
#define C_OUT 128   // 2*C

// Scratch (device globals — no allocations allowed)
__device__ float g_h[NMAX * C_OUT];     // 51.2 MB
__device__ float g_agg[NMAX * C_OUT];   // 51.2 MB
__device__ float g_x0[NMAX * C_IN];     // 25.6 MB
__device__ float g_x1[NMAX * C_IN];     // 25.6 MB
__device__ float g_deg[NMAX];
__device__ float g_dinv[NMAX];

__device__ __forceinline__ int clampi(int v, int lo, int hi) {
    return v < lo ? lo : (v > hi ? hi : v);
}

// ---------------- degree / dinv ----------------
__global__ void zero_deg_kernel(int n) {
    int i = blockIdx.x * blockDim.x + threadIdx.x;
    if (i < n) g_deg[i] = 0.0f;
}

__global__ void count_deg_kernel(const int* __restrict__ dst, int e, int n) {
    int i = blockIdx.x * blockDim.x + threadIdx.x;
    if (i < e) atomicAdd(&g_deg[clampi(dst[i], 0, n - 1)], 1.0f);
}

__global__ void dinv_kernel(int n) {
    int i = blockIdx.x * blockDim.x + threadIdx.x;
    if (i < n) g_dinv[i] = rsqrtf(g_deg[i] + 1.0f);
}

// ---------------- GEMM: h = x @ W ; agg = h * dinv^2 + b ----------------
// blockDim = 128 (one thread per output column), 8 rows per block.
__global__ void __launch_bounds__(128)
gemm_self_kernel(const float* __restrict__ x,
                 const float* __restrict__ W,    // [64,128] row-major
                 const float* __restrict__ b,    // [128]
                 int n) {
    __shared__ float ws[C_IN * C_OUT];   // 32 KB
    __shared__ float xs[8][C_IN];        // 2 KB

    const int j = threadIdx.x;           // output column 0..127
    const int r0 = blockIdx.x * 8;

    // load W
    for (int t = j; t < C_IN * C_OUT; t += 128) ws[t] = W[t];
    // load 8 rows of x
    for (int t = j; t < 8 * C_IN; t += 128) {
        int r = t >> 6, k = t & 63;
        xs[r][k] = (r0 + r < n) ? x[(size_t)(r0 + r) * C_IN + k] : 0.0f;
    }
    __syncthreads();

    const float bj = b[j];
    #pragma unroll
    for (int r = 0; r < 8; r++) {
        int row = r0 + r;
        if (row >= n) break;
        float acc = 0.0f;
        #pragma unroll
        for (int k = 0; k < C_IN; k++)
            acc = fmaf(xs[r][k], ws[k * C_OUT + j], acc);
        float dv = g_dinv[row];
        g_h[(size_t)row * C_OUT + j]   = acc;
        g_agg[(size_t)row * C_OUT + j] = fmaf(acc, dv * dv, bj);
    }
}

// ---------------- edge scatter: agg[dst] += h[src] * coef ----------------
// one warp per edge; each lane handles a float4 (32*4 = 128 floats)
__global__ void __launch_bounds__(256)
scatter_kernel(const int* __restrict__ src,
               const int* __restrict__ dst,
               int e, int n) {
    int warp = (blockIdx.x * blockDim.x + threadIdx.x) >> 5;
    int lane = threadIdx.x & 31;
    if (warp >= e) return;
    int s = clampi(src[warp], 0, n - 1);
    int d = clampi(dst[warp], 0, n - 1);
    float coef = g_dinv[s] * g_dinv[d];
    const float4* hp = reinterpret_cast<const float4*>(g_h + (size_t)s * C_OUT);
    float4 v = hp[lane];
    float* ap = g_agg + (size_t)d * C_OUT + lane * 4;
    atomicAdd(ap + 0, v.x * coef);
    atomicAdd(ap + 1, v.y * coef);
    atomicAdd(ap + 2, v.z * coef);
    atomicAdd(ap + 3, v.w * coef);
}

// ---------------- epilogue: GLU + residual ----------------
__global__ void __launch_bounds__(256)
glu_kernel(const float* __restrict__ xin, float* __restrict__ xout, int n) {
    int i = blockIdx.x * blockDim.x + threadIdx.x;
    if (i >= n * C_IN) return;
    int row = i >> 6, c = i & 63;
    float a = g_agg[(size_t)row * C_OUT + c];
    float g = g_agg[(size_t)row * C_OUT + 64 + c];
    float sig = 1.0f / (1.0f + __expf(-g));
    xout[i] = fmaf(a, sig, xin[i]);
}

extern "C" void kernel_launch(void* const* d_in, const int* in_sizes, int n_in,
                              void* d_out, int out_size) {
    // Identify inputs by SIZE (robust to metadata ordering):
    //   x          : size == out_size             (N*64   = 6,400,000) float32
    //   edge_index : largest remaining            (2*E    = 3,200,000) int32
    //   Ws         : middle remaining             (L*64*128 = 24,576)  float32
    //   bs         : smallest remaining           (L*128  = 384)       float32
    const float* x = nullptr;
    const float* Ws = nullptr;
    const float* bs = nullptr;
    const int* ei = nullptr;
    int ei_elems = 0, Ws_elems = 0;

    int used[16] = {0};
    for (int i = 0; i < n_in; i++) {
        if (!x && in_sizes[i] == out_size) { x = (const float*)d_in[i]; used[i] = 1; break; }
    }
    {   // edge_index: largest unused
        int best = -1, bsz = -1;
        for (int i = 0; i < n_in; i++)
            if (!used[i] && in_sizes[i] > bsz) { bsz = in_sizes[i]; best = i; }
        ei = (const int*)d_in[best]; ei_elems = bsz; used[best] = 1;
    }
    {   // Ws: largest of remaining
        int best = -1, bsz = -1;
        for (int i = 0; i < n_in; i++)
            if (!used[i] && in_sizes[i] > bsz) { bsz = in_sizes[i]; best = i; }
        Ws = (const float*)d_in[best]; Ws_elems = bsz; used[best] = 1;
    }
    for (int i = 0; i < n_in; i++)  // bs: leftover
        if (!used[i]) { bs = (const float*)d_in[i]; used[i] = 1; break; }

    const int n = out_size / C_IN;
    const int e = ei_elems / 2;
    const int L = Ws_elems / (C_IN * C_OUT);

    const int* src = ei;        // edge_index[0] = row 0
    const int* dst = ei + e;    // edge_index[1] = row 1

    float *x0, *x1;
    cudaGetSymbolAddress((void**)&x0, g_x0);
    cudaGetSymbolAddress((void**)&x1, g_x1);

    // degree + dinv
    zero_deg_kernel<<<(n + 255) / 256, 256>>>(n);
    count_deg_kernel<<<(e + 255) / 256, 256>>>(dst, e, n);
    dinv_kernel<<<(n + 255) / 256, 256>>>(n);

    const float* xin = x;
    for (int l = 0; l < L; l++) {
        float* xout = (l == L - 1) ? (float*)d_out : ((l & 1) ? x1 : x0);

        gemm_self_kernel<<<(n + 7) / 8, 128>>>(
            xin, Ws + (size_t)l * C_IN * C_OUT, bs + (size_t)l * C_OUT, n);

        // 8 warps per block -> 8 edges per block
        scatter_kernel<<<(e + 7) / 8, 256>>>(src, dst, e, n);

        glu_kernel<<<(n * C_IN + 255) / 256, 256>>>(xin, xout, n);

        xin = xout;
    }
}

// round 4
// speedup vs baseline: 3.8640x; 3.8640x over previous
#include <cuda_runtime.h>
#include <math.h>

#define NMAX 100000
#define EMAX 1600000
#define C_IN 64
#define C_OUT 128
#define NB_SCAN ((NMAX + 1023) / 1024)

// Scratch (device globals — no allocations allowed)
__device__ float g_h[(size_t)NMAX * C_OUT];   // 51.2 MB
__device__ float g_x0[(size_t)NMAX * C_IN];   // 25.6 MB
__device__ float g_x1[(size_t)NMAX * C_IN];   // 25.6 MB
__device__ float g_dinv[NMAX];
__device__ int   g_cnt[NMAX];
__device__ int   g_rowstart[NMAX + 1];
__device__ int   g_srcid[EMAX];               // 6.4 MB
__device__ float g_coef[EMAX];                // 6.4 MB
__device__ int   g_blocksum[NB_SCAN];
__device__ int   g_blockoff[NB_SCAN];

__device__ __forceinline__ int clampi(int v, int lo, int hi) {
    return v < lo ? lo : (v > hi ? hi : v);
}

// ---------------- CSR build ----------------
__global__ void zero_cnt_kernel(int n) {
    int i = blockIdx.x * blockDim.x + threadIdx.x;
    if (i < n) g_cnt[i] = 0;
}

__global__ void count_kernel(const int* __restrict__ dst, int e, int n) {
    int i = blockIdx.x * blockDim.x + threadIdx.x;
    if (i < e) atomicAdd(&g_cnt[clampi(dst[i], 0, n - 1)], 1);
}

__global__ void dinv_kernel(int n) {
    int i = blockIdx.x * blockDim.x + threadIdx.x;
    if (i < n) g_dinv[i] = rsqrtf((float)g_cnt[i] + 1.0f);
}

// block-level inclusive scan -> exclusive rowstart + per-block sums
__global__ void __launch_bounds__(1024) scan1_kernel(int n) {
    __shared__ int sm[1024];
    int i = blockIdx.x * 1024 + threadIdx.x;
    int v = (i < n) ? g_cnt[i] : 0;
    sm[threadIdx.x] = v;
    __syncthreads();
    #pragma unroll
    for (int off = 1; off < 1024; off <<= 1) {
        int t = (threadIdx.x >= off) ? sm[threadIdx.x - off] : 0;
        __syncthreads();
        sm[threadIdx.x] += t;
        __syncthreads();
    }
    if (i < n) g_rowstart[i] = sm[threadIdx.x] - v;   // exclusive
    if (threadIdx.x == 1023) g_blocksum[blockIdx.x] = sm[1023];
}

__global__ void scan2_kernel(int nb, int n) {
    if (threadIdx.x == 0 && blockIdx.x == 0) {
        int run = 0;
        for (int b = 0; b < nb; b++) { g_blockoff[b] = run; run += g_blocksum[b]; }
        g_rowstart[n] = run;
    }
}

__global__ void __launch_bounds__(1024) scan3_kernel(int n) {
    int i = blockIdx.x * 1024 + threadIdx.x;
    if (i < n) g_rowstart[i] += g_blockoff[blockIdx.x];
}

__global__ void fill_kernel(const int* __restrict__ src,
                            const int* __restrict__ dst, int e, int n) {
    int i = blockIdx.x * blockDim.x + threadIdx.x;
    if (i >= e) return;
    int s = clampi(src[i], 0, n - 1);
    int d = clampi(dst[i], 0, n - 1);
    int pos = g_rowstart[d] + atomicAdd(&g_cnt[d], 1);
    g_srcid[pos] = s;
    g_coef[pos]  = g_dinv[s] * g_dinv[d];
}

// ---------------- GEMM: h = x @ W (register-tiled) ----------------
// 128 threads (one per output col), 16 rows per block.
__global__ void __launch_bounds__(128)
gemm_kernel(const float* __restrict__ x, const float* __restrict__ W, int n) {
    __shared__ float  ws[C_IN * C_OUT];    // 32 KB
    __shared__ float4 xs[16][16];          // 16 rows x 64 floats = 4 KB

    const int j = threadIdx.x;
    const int row0 = blockIdx.x * 16;

    const float4* W4 = reinterpret_cast<const float4*>(W);
    float4* ws4 = reinterpret_cast<float4*>(ws);
    #pragma unroll
    for (int t = 0; t < 16; t++) ws4[t * 128 + j] = W4[t * 128 + j];

    const float4* x4 = reinterpret_cast<const float4*>(x);
    #pragma unroll
    for (int t = j; t < 256; t += 128) {
        int r = t >> 4, k4 = t & 15;
        int row = row0 + r;
        xs[r][k4] = (row < n) ? x4[(size_t)row * 16 + k4]
                              : make_float4(0.f, 0.f, 0.f, 0.f);
    }
    __syncthreads();

    float w[C_IN];
    #pragma unroll
    for (int k = 0; k < C_IN; k++) w[k] = ws[k * C_OUT + j];

    #pragma unroll
    for (int r = 0; r < 16; r++) {
        int row = row0 + r;
        if (row >= n) break;
        float acc = 0.0f;
        #pragma unroll
        for (int k4 = 0; k4 < 16; k4++) {
            float4 xv = xs[r][k4];
            acc = fmaf(xv.x, w[4 * k4 + 0], acc);
            acc = fmaf(xv.y, w[4 * k4 + 1], acc);
            acc = fmaf(xv.z, w[4 * k4 + 2], acc);
            acc = fmaf(xv.w, w[4 * k4 + 3], acc);
        }
        g_h[(size_t)row * C_OUT + j] = acc;
    }
}

// ---------------- fused aggregate + self + bias + GLU + residual ----------
// one warp per node; lane holds float4 = cols 4L..4L+3 of the 128-wide row.
__global__ void __launch_bounds__(256)
agg_glu_kernel(const float* __restrict__ xin, float* __restrict__ xout,
               const float* __restrict__ b, int n) {
    int node = (blockIdx.x * blockDim.x + threadIdx.x) >> 5;
    int lane = threadIdx.x & 31;
    if (node >= n) return;

    const float4* h4 = reinterpret_cast<const float4*>(g_h);
    const float4* b4 = reinterpret_cast<const float4*>(b);

    float dv = g_dinv[node];
    float s2 = dv * dv;
    float4 acc = h4[(size_t)node * 32 + lane];
    float4 bb = b4[lane];
    acc.x = fmaf(acc.x, s2, bb.x);
    acc.y = fmaf(acc.y, s2, bb.y);
    acc.z = fmaf(acc.z, s2, bb.z);
    acc.w = fmaf(acc.w, s2, bb.w);

    int r0 = g_rowstart[node];
    int r1 = g_rowstart[node + 1];
    for (int base = r0; base < r1; base += 32) {
        int m = r1 - base; if (m > 32) m = 32;
        int sid = 0; float cf = 0.0f;
        if (lane < m) { sid = g_srcid[base + lane]; cf = g_coef[base + lane]; }
        for (int t = 0; t < m; t++) {
            int   s = __shfl_sync(0xffffffffu, sid, t);
            float c = __shfl_sync(0xffffffffu, cf,  t);
            float4 v = h4[(size_t)s * 32 + lane];
            acc.x = fmaf(v.x, c, acc.x);
            acc.y = fmaf(v.y, c, acc.y);
            acc.z = fmaf(v.z, c, acc.z);
            acc.w = fmaf(v.w, c, acc.w);
        }
    }

    // GLU: a = cols 0..63 (lanes 0..15), g = cols 64..127 (lanes 16..31)
    float gx = __shfl_sync(0xffffffffu, acc.x, (lane + 16) & 31);
    float gy = __shfl_sync(0xffffffffu, acc.y, (lane + 16) & 31);
    float gz = __shfl_sync(0xffffffffu, acc.z, (lane + 16) & 31);
    float gw = __shfl_sync(0xffffffffu, acc.w, (lane + 16) & 31);

    if (lane < 16) {
        float4 r = reinterpret_cast<const float4*>(xin)[(size_t)node * 16 + lane];
        float4 o;
        o.x = fmaf(acc.x, __frcp_rn(1.0f + expf(-gx)), r.x);
        o.y = fmaf(acc.y, __frcp_rn(1.0f + expf(-gy)), r.y);
        o.z = fmaf(acc.z, __frcp_rn(1.0f + expf(-gz)), r.z);
        o.w = fmaf(acc.w, __frcp_rn(1.0f + expf(-gw)), r.w);
        reinterpret_cast<float4*>(xout)[(size_t)node * 16 + lane] = o;
    }
}

extern "C" void kernel_launch(void* const* d_in, const int* in_sizes, int n_in,
                              void* d_out, int out_size) {
    // Identify inputs by SIZE:
    //   x: == out_size (6.4M f32); edge_index: largest rest (3.2M i32);
    //   Ws: next (24576 f32); bs: smallest (384 f32)
    const float* x = nullptr; const float* Ws = nullptr; const float* bs = nullptr;
    const int* ei = nullptr;
    int ei_elems = 0, Ws_elems = 0;
    int used[16] = {0};
    for (int i = 0; i < n_in; i++)
        if (!x && in_sizes[i] == out_size) { x = (const float*)d_in[i]; used[i] = 1; break; }
    {
        int best = -1, bsz = -1;
        for (int i = 0; i < n_in; i++)
            if (!used[i] && in_sizes[i] > bsz) { bsz = in_sizes[i]; best = i; }
        ei = (const int*)d_in[best]; ei_elems = bsz; used[best] = 1;
    }
    {
        int best = -1, bsz = -1;
        for (int i = 0; i < n_in; i++)
            if (!used[i] && in_sizes[i] > bsz) { bsz = in_sizes[i]; best = i; }
        Ws = (const float*)d_in[best]; Ws_elems = bsz; used[best] = 1;
    }
    for (int i = 0; i < n_in; i++)
        if (!used[i]) { bs = (const float*)d_in[i]; used[i] = 1; break; }

    const int n = out_size / C_IN;
    const int e = ei_elems / 2;
    const int L = Ws_elems / (C_IN * C_OUT);
    const int* src = ei;
    const int* dst = ei + e;
    const int nb = (n + 1023) / 1024;

    float *x0, *x1;
    cudaGetSymbolAddress((void**)&x0, g_x0);
    cudaGetSymbolAddress((void**)&x1, g_x1);

    // ---- CSR build (once) ----
    zero_cnt_kernel<<<(n + 255) / 256, 256>>>(n);
    count_kernel<<<(e + 255) / 256, 256>>>(dst, e, n);
    dinv_kernel<<<(n + 255) / 256, 256>>>(n);
    scan1_kernel<<<nb, 1024>>>(n);
    scan2_kernel<<<1, 32>>>(nb, n);
    scan3_kernel<<<nb, 1024>>>(n);
    zero_cnt_kernel<<<(n + 255) / 256, 256>>>(n);
    fill_kernel<<<(e + 255) / 256, 256>>>(src, dst, e, n);

    // ---- layers ----
    const float* xin = x;
    for (int l = 0; l < L; l++) {
        float* xout = (l == L - 1) ? (float*)d_out : ((l & 1) ? x1 : x0);
        gemm_kernel<<<(n + 15) / 16, 128>>>(
            xin, Ws + (size_t)l * C_IN * C_OUT, n);
        agg_glu_kernel<<<(n * 32 + 255) / 256, 256>>>(
            xin, xout, bs + (size_t)l * C_OUT, n);
        xin = xout;
    }
}

// round 5
// speedup vs baseline: 4.1640x; 1.0776x over previous
#include <cuda_runtime.h>
#include <math.h>

#define NMAX 100000
#define EMAX 1600000
#define C_IN 64
#define C_OUT 128
#define NB_SCAN ((NMAX + 1023) / 1024)

// Scratch (device globals — no allocations allowed)
__device__ float g_y[(size_t)NMAX * C_IN];    // 25.6 MB aggregated features
__device__ float g_x0[(size_t)NMAX * C_IN];   // 25.6 MB ping
__device__ float g_x1[(size_t)NMAX * C_IN];   // 25.6 MB pong
__device__ float g_dinv[NMAX];
__device__ int   g_cnt[NMAX];
__device__ int   g_rowstart[NMAX + 1];
__device__ int2  g_edge[EMAX];                // {srcid, coef bits} 12.8 MB
__device__ int   g_blocksum[NB_SCAN];
__device__ int   g_blockoff[NB_SCAN];

__device__ __forceinline__ int clampi(int v, int lo, int hi) {
    return v < lo ? lo : (v > hi ? hi : v);
}

// ---------------- CSR build ----------------
__global__ void zero_cnt_kernel(int n) {
    int i = blockIdx.x * blockDim.x + threadIdx.x;
    if (i < n) g_cnt[i] = 0;
}

__global__ void count_kernel(const int* __restrict__ dst, int e, int n) {
    int i = blockIdx.x * blockDim.x + threadIdx.x;
    if (i < e) atomicAdd(&g_cnt[clampi(dst[i], 0, n - 1)], 1);
}

__global__ void dinv_kernel(int n) {
    int i = blockIdx.x * blockDim.x + threadIdx.x;
    if (i < n) g_dinv[i] = rsqrtf((float)g_cnt[i] + 1.0f);
}

__global__ void __launch_bounds__(1024) scan1_kernel(int n) {
    __shared__ int sm[1024];
    int i = blockIdx.x * 1024 + threadIdx.x;
    int v = (i < n) ? g_cnt[i] : 0;
    sm[threadIdx.x] = v;
    __syncthreads();
    #pragma unroll
    for (int off = 1; off < 1024; off <<= 1) {
        int t = (threadIdx.x >= off) ? sm[threadIdx.x - off] : 0;
        __syncthreads();
        sm[threadIdx.x] += t;
        __syncthreads();
    }
    if (i < n) g_rowstart[i] = sm[threadIdx.x] - v;   // exclusive
    if (threadIdx.x == 1023) g_blocksum[blockIdx.x] = sm[1023];
}

__global__ void scan2_kernel(int nb, int n) {
    if (threadIdx.x == 0 && blockIdx.x == 0) {
        int run = 0;
        for (int b = 0; b < nb; b++) { g_blockoff[b] = run; run += g_blocksum[b]; }
        g_rowstart[n] = run;
    }
}

__global__ void __launch_bounds__(1024) scan3_kernel(int n) {
    int i = blockIdx.x * 1024 + threadIdx.x;
    if (i < n) g_rowstart[i] += g_blockoff[blockIdx.x];
}

__global__ void fill_kernel(const int* __restrict__ src,
                            const int* __restrict__ dst, int e, int n) {
    int i = blockIdx.x * blockDim.x + threadIdx.x;
    if (i >= e) return;
    int s = clampi(src[i], 0, n - 1);
    int d = clampi(dst[i], 0, n - 1);
    int pos = g_rowstart[d] + atomicAdd(&g_cnt[d], 1);
    float coef = g_dinv[s] * g_dinv[d];
    g_edge[pos] = make_int2(s, __float_as_int(coef));
}

// ---------------- aggregate in x-space (64 ch) ----------------
// one warp per node; lane holds float2 = cols 2L..2L+1
__global__ void __launch_bounds__(256)
agg_kernel(const float* __restrict__ xin, int n) {
    int node = (blockIdx.x * blockDim.x + threadIdx.x) >> 5;
    int lane = threadIdx.x & 31;
    if (node >= n) return;

    const float2* x2 = reinterpret_cast<const float2*>(xin);
    float dv = g_dinv[node];
    float s2 = dv * dv;
    float2 acc = x2[(size_t)node * 32 + lane];
    acc.x *= s2; acc.y *= s2;

    int r0 = g_rowstart[node];
    int r1 = g_rowstart[node + 1];
    for (int base = r0; base < r1; base += 32) {
        int m = r1 - base; if (m > 32) m = 32;
        int sid = 0; float cf = 0.0f;
        if (lane < m) {
            int2 ed = g_edge[base + lane];
            sid = ed.x; cf = __int_as_float(ed.y);
        }
        for (int t = 0; t < m; t++) {
            int   s = __shfl_sync(0xffffffffu, sid, t);
            float c = __shfl_sync(0xffffffffu, cf,  t);
            float2 v = x2[(size_t)s * 32 + lane];
            acc.x = fmaf(v.x, c, acc.x);
            acc.y = fmaf(v.y, c, acc.y);
        }
    }
    reinterpret_cast<float2*>(g_y)[(size_t)node * 32 + lane] = acc;
}

// ---------------- fused GEMM + bias + GLU + residual ----------------
// 128 threads: thread j computes output col j of h=y@W+b for 32 rows,
// exchanges through smem, then GLU + residual.
#define ROWS_PB 32
__global__ void __launch_bounds__(128)
gemm_glu_kernel(const float* __restrict__ xin, float* __restrict__ xout,
                const float* __restrict__ W, const float* __restrict__ b,
                int n) {
    __shared__ float4 ys[ROWS_PB][16];      // 8 KB  (y rows)
    __shared__ float  hs[ROWS_PB][C_OUT];   // 16 KB (h tile)

    const int j = threadIdx.x;
    const int row0 = blockIdx.x * ROWS_PB;

    // W column j into registers
    float w[C_IN];
    #pragma unroll
    for (int k = 0; k < C_IN; k++) w[k] = W[k * C_OUT + j];
    const float bj = b[j];

    // load y rows
    const float4* y4 = reinterpret_cast<const float4*>(g_y);
    #pragma unroll
    for (int t = j; t < ROWS_PB * 16; t += 128) {
        int r = t >> 4, k4 = t & 15;
        int row = row0 + r;
        ys[r][k4] = (row < n) ? y4[(size_t)row * 16 + k4]
                              : make_float4(0.f, 0.f, 0.f, 0.f);
    }
    __syncthreads();

    #pragma unroll 4
    for (int r = 0; r < ROWS_PB; r++) {
        float acc = bj;
        #pragma unroll
        for (int k4 = 0; k4 < 16; k4++) {
            float4 yv = ys[r][k4];
            acc = fmaf(yv.x, w[4 * k4 + 0], acc);
            acc = fmaf(yv.y, w[4 * k4 + 1], acc);
            acc = fmaf(yv.z, w[4 * k4 + 2], acc);
            acc = fmaf(yv.w, w[4 * k4 + 3], acc);
        }
        hs[r][j] = acc;
    }
    __syncthreads();

    // GLU + residual: thread j -> col c=j&63, rows (j>>6)*16 .. +15
    const int c = j & 63;
    const int rbase = (j >> 6) * (ROWS_PB / 2);
    #pragma unroll
    for (int rr = 0; rr < ROWS_PB / 2; rr++) {
        int r = rbase + rr;
        int row = row0 + r;
        if (row >= n) break;
        float a = hs[r][c];
        float g = hs[r][c + 64];
        float sig = 1.0f / (1.0f + expf(-g));
        float res = xin[(size_t)row * C_IN + c];
        xout[(size_t)row * C_IN + c] = fmaf(a, sig, res);
    }
}

extern "C" void kernel_launch(void* const* d_in, const int* in_sizes, int n_in,
                              void* d_out, int out_size) {
    // Identify inputs by SIZE:
    //   x: == out_size (6.4M f32); edge_index: largest rest (3.2M i32);
    //   Ws: next (24576 f32); bs: smallest (384 f32)
    const float* x = nullptr; const float* Ws = nullptr; const float* bs = nullptr;
    const int* ei = nullptr;
    int ei_elems = 0, Ws_elems = 0;
    int used[16] = {0};
    for (int i = 0; i < n_in; i++)
        if (!x && in_sizes[i] == out_size) { x = (const float*)d_in[i]; used[i] = 1; break; }
    {
        int best = -1, bsz = -1;
        for (int i = 0; i < n_in; i++)
            if (!used[i] && in_sizes[i] > bsz) { bsz = in_sizes[i]; best = i; }
        ei = (const int*)d_in[best]; ei_elems = bsz; used[best] = 1;
    }
    {
        int best = -1, bsz = -1;
        for (int i = 0; i < n_in; i++)
            if (!used[i] && in_sizes[i] > bsz) { bsz = in_sizes[i]; best = i; }
        Ws = (const float*)d_in[best]; Ws_elems = bsz; used[best] = 1;
    }
    for (int i = 0; i < n_in; i++)
        if (!used[i]) { bs = (const float*)d_in[i]; used[i] = 1; break; }

    const int n = out_size / C_IN;
    const int e = ei_elems / 2;
    const int L = Ws_elems / (C_IN * C_OUT);
    const int* src = ei;
    const int* dst = ei + e;
    const int nb = (n + 1023) / 1024;

    float *x0, *x1;
    cudaGetSymbolAddress((void**)&x0, g_x0);
    cudaGetSymbolAddress((void**)&x1, g_x1);

    // ---- CSR build (once per call) ----
    zero_cnt_kernel<<<(n + 255) / 256, 256>>>(n);
    count_kernel<<<(e + 255) / 256, 256>>>(dst, e, n);
    dinv_kernel<<<(n + 255) / 256, 256>>>(n);
    scan1_kernel<<<nb, 1024>>>(n);
    scan2_kernel<<<1, 32>>>(nb, n);
    scan3_kernel<<<nb, 1024>>>(n);
    zero_cnt_kernel<<<(n + 255) / 256, 256>>>(n);
    fill_kernel<<<(e + 255) / 256, 256>>>(src, dst, e, n);

    // ---- layers ----
    const float* xin = x;
    for (int l = 0; l < L; l++) {
        float* xout = (l == L - 1) ? (float*)d_out : ((l & 1) ? x1 : x0);
        agg_kernel<<<(n * 32 + 255) / 256, 256>>>(xin, n);
        gemm_glu_kernel<<<(n + ROWS_PB - 1) / ROWS_PB, 128>>>(
            xin, xout, Ws + (size_t)l * C_IN * C_OUT, bs + (size_t)l * C_OUT, n);
        xin = xout;
    }
}